// round 1
// baseline (speedup 1.0000x reference)
#include <cuda_runtime.h>
#include <math.h>

#define BATCH 8
#define N1 2048
#define N2 2048
#define KPT 128
#define THREADS 256
#define TILE 256

// slot layout:
//   [0..63]    dir0: pts -> recon  (min over recon per pt),  weight 0.5/(B*N1)
//   [64..127]  dir1: recon -> pts, weight 0.5/(B*N2)
//   [128..191] dir2: pts -> kpt   (min over kpt per pt),    weight 0.5/(B*N1)
//   [192..255] dir3: kpt -> pts   (min over pts per kpt),   weight 0.5/(B*KPT)
//   [256..263] per-batch small losses (pose + nocs + diversity + delta), pre-normalized
__device__ float g_slots[264];

__global__ void chamfer_kernel(const float* __restrict__ pts,
                               const float* __restrict__ recon,
                               const float* __restrict__ kpt) {
    const int dir = blockIdx.z;
    const float* Q; const float* T; int NQ, NT; float w;
    if (dir == 0)      { Q = pts;   T = recon; NQ = N1;  NT = N2;  w = 0.5f / (BATCH * N1);  }
    else if (dir == 1) { Q = recon; T = pts;   NQ = N2;  NT = N1;  w = 0.5f / (BATCH * N2);  }
    else if (dir == 2) { Q = pts;   T = kpt;   NQ = N1;  NT = KPT; w = 0.5f / (BATCH * N1);  }
    else               { Q = kpt;   T = pts;   NQ = KPT; NT = N1;  w = 0.5f / (BATCH * KPT); }

    const int b = blockIdx.y;
    const int slot = dir * 64 + b * 8 + blockIdx.x;

    // blocks entirely beyond NQ (dir3 has only 128 rows): write zero and exit.
    if (blockIdx.x * THREADS >= NQ) {
        if (threadIdx.x == 0) g_slots[slot] = 0.0f;
        return;
    }

    Q += (size_t)b * NQ * 3;
    T += (size_t)b * NT * 3;

    const int row = blockIdx.x * THREADS + threadIdx.x;
    const bool valid = row < NQ;
    float qx = 0.f, qy = 0.f, qz = 0.f;
    if (valid) {
        qx = Q[row * 3 + 0];
        qy = Q[row * 3 + 1];
        qz = Q[row * 3 + 2];
    }

    __shared__ float sx[TILE], sy[TILE], sz[TILE];
    float m = 3.0e38f;

    for (int j0 = 0; j0 < NT; j0 += TILE) {
        const int j = j0 + threadIdx.x;
        if (j < NT) {
            sx[threadIdx.x] = T[j * 3 + 0];
            sy[threadIdx.x] = T[j * 3 + 1];
            sz[threadIdx.x] = T[j * 3 + 2];
        }
        __syncthreads();
        const int lim = min(TILE, NT - j0);
        #pragma unroll 8
        for (int jj = 0; jj < lim; jj++) {
            float dx = qx - sx[jj];
            float dy = qy - sy[jj];
            float dz = qz - sz[jj];
            float d2 = fmaf(dx, dx, fmaf(dy, dy, dz * dz));
            m = fminf(m, d2);
        }
        __syncthreads();
    }

    float v = valid ? sqrtf(m) * w : 0.0f;

    __shared__ float red[THREADS];
    red[threadIdx.x] = v;
    __syncthreads();
    #pragma unroll
    for (int s = THREADS / 2; s > 0; s >>= 1) {
        if (threadIdx.x < s) red[threadIdx.x] += red[threadIdx.x + s];
        __syncthreads();
    }
    if (threadIdx.x == 0) g_slots[slot] = red[0];
}

__global__ void small_losses_kernel(const float* __restrict__ recon_delta,
                                    const float* __restrict__ kpt,
                                    const float* __restrict__ pred_nocs,
                                    const float* __restrict__ pred_R,
                                    const float* __restrict__ pred_t,
                                    const float* __restrict__ pred_s,
                                    const float* __restrict__ gt_R,
                                    const float* __restrict__ gt_t,
                                    const float* __restrict__ gt_s) {
    const int b = blockIdx.x;
    const int tid = threadIdx.x;

    __shared__ float sk[KPT * 3];
    const float* K = kpt + (size_t)b * KPT * 3;
    for (int i = tid; i < KPT * 3; i += THREADS) sk[i] = K[i];
    __syncthreads();

    float acc = 0.0f;

    // diversity: pairwise kpt distances clamped at TH=0.1, diagonal -> TH
    const float invDiv = 1.0f / (float)(BATCH * KPT * KPT);
    for (int p = tid; p < KPT * KPT; p += THREADS) {
        const int i = p >> 7;
        const int j = p & 127;
        float c;
        if (i == j) {
            c = 0.1f;
        } else {
            float dx = sk[i * 3 + 0] - sk[j * 3 + 0];
            float dy = sk[i * 3 + 1] - sk[j * 3 + 1];
            float dz = sk[i * 3 + 2] - sk[j * 3 + 2];
            c = fminf(sqrtf(fmaf(dx, dx, fmaf(dy, dy, dz * dz))), 0.1f);
        }
        acc += c * invDiv;
    }

    // NOCS smooth-L1: one thread per keypoint
    if (tid < KPT) {
        const float* R = gt_R + (size_t)b * 9;
        const float t0 = gt_t[b * 3 + 0], t1 = gt_t[b * 3 + 1], t2 = gt_t[b * 3 + 2];
        const float s0 = gt_s[b * 3 + 0], s1 = gt_s[b * 3 + 1], s2 = gt_s[b * 3 + 2];
        const float scale = sqrtf(s0 * s0 + s1 * s1 + s2 * s2) + 1e-8f;
        const float inv = 1.0f / scale;
        const float px = (sk[tid * 3 + 0] - t0) * inv;
        const float py = (sk[tid * 3 + 1] - t1) * inv;
        const float pz = (sk[tid * 3 + 2] - t2) * inv;
        const float* pn = pred_nocs + ((size_t)b * KPT + tid) * 3;
        float sl = 0.0f;
        #pragma unroll
        for (int j = 0; j < 3; j++) {
            float g = px * R[j] + py * R[3 + j] + pz * R[6 + j];
            float d = fabsf(pn[j] - g);
            sl += (d > 0.1f) ? (d - 0.05f) : (d * d * 5.0f);
        }
        acc += sl * (1.0f / (float)(BATCH * KPT));
    }

    // delta magnitude regularizer
    const float* D = recon_delta + (size_t)b * N2 * 3;
    float dsum = 0.0f;
    for (int r = tid; r < N2; r += THREADS) {
        float x = D[r * 3 + 0];
        float y = D[r * 3 + 1];
        float z = D[r * 3 + 2];
        dsum += sqrtf(fmaf(x, x, fmaf(y, y, z * z)));
    }
    acc += dsum * (1.0f / (float)(BATCH * N2));

    __shared__ float red[THREADS];
    red[tid] = acc;
    __syncthreads();
    #pragma unroll
    for (int s = THREADS / 2; s > 0; s >>= 1) {
        if (tid < s) red[tid] += red[tid + s];
        __syncthreads();
    }

    if (tid == 0) {
        // pose loss (per batch): column norms of R diff + t norm + s norm
        const float* Rp = pred_R + (size_t)b * 9;
        const float* Rg = gt_R + (size_t)b * 9;
        float cs = 0.0f;
        #pragma unroll
        for (int j = 0; j < 3; j++) {
            float a0 = Rp[j]     - Rg[j];
            float a1 = Rp[3 + j] - Rg[3 + j];
            float a2 = Rp[6 + j] - Rg[6 + j];
            cs += sqrtf(a0 * a0 + a1 * a1 + a2 * a2);
        }
        float dt0 = pred_t[b * 3 + 0] - gt_t[b * 3 + 0];
        float dt1 = pred_t[b * 3 + 1] - gt_t[b * 3 + 1];
        float dt2 = pred_t[b * 3 + 2] - gt_t[b * 3 + 2];
        float tn = sqrtf(dt0 * dt0 + dt1 * dt1 + dt2 * dt2);
        float ds0 = pred_s[b * 3 + 0] - gt_s[b * 3 + 0];
        float ds1 = pred_s[b * 3 + 1] - gt_s[b * 3 + 1];
        float ds2 = pred_s[b * 3 + 2] - gt_s[b * 3 + 2];
        float sn = sqrtf(ds0 * ds0 + ds1 * ds1 + ds2 * ds2);
        float pose = cs * (1.0f / (3.0f * BATCH)) + tn * (1.0f / BATCH) + sn * (1.0f / BATCH);
        g_slots[256 + b] = red[0] + pose;
    }
}

__global__ void finalize_kernel(float* __restrict__ out) {
    float a = 0.0f;
    for (int i = threadIdx.x; i < 264; i += THREADS) a += g_slots[i];
    __shared__ float red[THREADS];
    red[threadIdx.x] = a;
    __syncthreads();
    #pragma unroll
    for (int s = THREADS / 2; s > 0; s >>= 1) {
        if (threadIdx.x < s) red[threadIdx.x] += red[threadIdx.x + s];
        __syncthreads();
    }
    if (threadIdx.x == 0) out[0] = red[0];
}

extern "C" void kernel_launch(void* const* d_in, const int* in_sizes, int n_in,
                              void* d_out, int out_size) {
    const float* pts         = (const float*)d_in[0];
    const float* recon_delta = (const float*)d_in[1];
    const float* kpt         = (const float*)d_in[2];
    const float* recon       = (const float*)d_in[3];
    const float* pred_nocs   = (const float*)d_in[4];
    const float* pred_R      = (const float*)d_in[5];
    const float* pred_t      = (const float*)d_in[6];
    const float* pred_s      = (const float*)d_in[7];
    const float* gt_R        = (const float*)d_in[8];
    const float* gt_t        = (const float*)d_in[9];
    const float* gt_s        = (const float*)d_in[10];

    chamfer_kernel<<<dim3(8, 8, 4), THREADS>>>(pts, recon, kpt);
    small_losses_kernel<<<BATCH, THREADS>>>(recon_delta, kpt, pred_nocs,
                                            pred_R, pred_t, pred_s,
                                            gt_R, gt_t, gt_s);
    finalize_kernel<<<1, THREADS>>>((float*)d_out);
}

// round 2
// speedup vs baseline: 1.3304x; 1.3304x over previous
#include <cuda_runtime.h>
#include <math.h>

#define BATCH 8
#define N1 2048
#define N2 2048
#define KPT 128
#define THREADS 256
#define TILE 256

// slot layout (256 slots):
//   dir*64 + b*8 + chunk
//   dir0: pts -> recon   weight 0.5/(B*N1)
//   dir1: recon -> pts   weight 0.5/(B*N2)
//   dir2: pts -> kpt     weight 0.5/(B*N1)
//   dir3: chunk0 = kpt -> pts (weight 0.5/(B*KPT)); chunk1 = per-batch small losses;
//         chunks 2..7 = 0
__device__ float g_slots[256];

__global__ void fused_kernel(const float* __restrict__ pts,
                             const float* __restrict__ recon,
                             const float* __restrict__ kpt,
                             const float* __restrict__ recon_delta,
                             const float* __restrict__ pred_nocs,
                             const float* __restrict__ pred_R,
                             const float* __restrict__ pred_t,
                             const float* __restrict__ pred_s,
                             const float* __restrict__ gt_R,
                             const float* __restrict__ gt_t,
                             const float* __restrict__ gt_s) {
    __shared__ __align__(16) float pool[TILE * 4];
    float* sx = pool;
    float* sy = pool + TILE;
    float* sz = pool + 2 * TILE;
    float* sw = pool + 3 * TILE;
    __shared__ float red[THREADS];

    const int dir = blockIdx.z;
    const int b   = blockIdx.y;
    const int tid = threadIdx.x;
    const int slot = dir * 64 + b * 8 + blockIdx.x;

    // ---------------- small-losses path (dir3, chunk1) ----------------
    if (dir == 3 && blockIdx.x == 1) {
        float* sk = pool;  // 384 floats for keypoints
        const float* K = kpt + (size_t)b * KPT * 3;
        for (int i = tid; i < KPT * 3; i += THREADS) sk[i] = K[i];
        __syncthreads();

        float acc = 0.0f;

        // diversity
        const float invDiv = 1.0f / (float)(BATCH * KPT * KPT);
        for (int p = tid; p < KPT * KPT; p += THREADS) {
            const int i = p >> 7;
            const int j = p & 127;
            float c;
            if (i == j) {
                c = 0.1f;
            } else {
                float dx = sk[i * 3 + 0] - sk[j * 3 + 0];
                float dy = sk[i * 3 + 1] - sk[j * 3 + 1];
                float dz = sk[i * 3 + 2] - sk[j * 3 + 2];
                c = fminf(sqrtf(fmaf(dx, dx, fmaf(dy, dy, dz * dz))), 0.1f);
            }
            acc += c * invDiv;
        }

        // NOCS smooth-L1
        if (tid < KPT) {
            const float* R = gt_R + (size_t)b * 9;
            const float t0 = gt_t[b * 3 + 0], t1 = gt_t[b * 3 + 1], t2 = gt_t[b * 3 + 2];
            const float s0 = gt_s[b * 3 + 0], s1 = gt_s[b * 3 + 1], s2 = gt_s[b * 3 + 2];
            const float scale = sqrtf(s0 * s0 + s1 * s1 + s2 * s2) + 1e-8f;
            const float inv = 1.0f / scale;
            const float px = (sk[tid * 3 + 0] - t0) * inv;
            const float py = (sk[tid * 3 + 1] - t1) * inv;
            const float pz = (sk[tid * 3 + 2] - t2) * inv;
            const float* pn = pred_nocs + ((size_t)b * KPT + tid) * 3;
            float sl = 0.0f;
            #pragma unroll
            for (int j = 0; j < 3; j++) {
                float g = px * R[j] + py * R[3 + j] + pz * R[6 + j];
                float d = fabsf(pn[j] - g);
                sl += (d > 0.1f) ? (d - 0.05f) : (d * d * 5.0f);
            }
            acc += sl * (1.0f / (float)(BATCH * KPT));
        }

        // delta regularizer
        const float* D = recon_delta + (size_t)b * N2 * 3;
        float dsum = 0.0f;
        for (int r = tid; r < N2; r += THREADS) {
            float x = D[r * 3 + 0];
            float y = D[r * 3 + 1];
            float z = D[r * 3 + 2];
            dsum += sqrtf(fmaf(x, x, fmaf(y, y, z * z)));
        }
        acc += dsum * (1.0f / (float)(BATCH * N2));

        red[tid] = acc;
        __syncthreads();
        #pragma unroll
        for (int s = THREADS / 2; s > 0; s >>= 1) {
            if (tid < s) red[tid] += red[tid + s];
            __syncthreads();
        }

        if (tid == 0) {
            const float* Rp = pred_R + (size_t)b * 9;
            const float* Rg = gt_R + (size_t)b * 9;
            float cs = 0.0f;
            #pragma unroll
            for (int j = 0; j < 3; j++) {
                float a0 = Rp[j]     - Rg[j];
                float a1 = Rp[3 + j] - Rg[3 + j];
                float a2 = Rp[6 + j] - Rg[6 + j];
                cs += sqrtf(a0 * a0 + a1 * a1 + a2 * a2);
            }
            float dt0 = pred_t[b * 3 + 0] - gt_t[b * 3 + 0];
            float dt1 = pred_t[b * 3 + 1] - gt_t[b * 3 + 1];
            float dt2 = pred_t[b * 3 + 2] - gt_t[b * 3 + 2];
            float tn = sqrtf(dt0 * dt0 + dt1 * dt1 + dt2 * dt2);
            float ds0 = pred_s[b * 3 + 0] - gt_s[b * 3 + 0];
            float ds1 = pred_s[b * 3 + 1] - gt_s[b * 3 + 1];
            float ds2 = pred_s[b * 3 + 2] - gt_s[b * 3 + 2];
            float sn = sqrtf(ds0 * ds0 + ds1 * ds1 + ds2 * ds2);
            g_slots[slot] = red[0]
                          + cs * (1.0f / (3.0f * BATCH))
                          + tn * (1.0f / BATCH)
                          + sn * (1.0f / BATCH);
        }
        return;
    }

    // ---------------- chamfer path ----------------
    const float* Q; const float* T; int NQ, NT; float w;
    if (dir == 0)      { Q = pts;   T = recon; NQ = N1;  NT = N2;  w = 0.5f / (BATCH * N1);  }
    else if (dir == 1) { Q = recon; T = pts;   NQ = N2;  NT = N1;  w = 0.5f / (BATCH * N2);  }
    else if (dir == 2) { Q = pts;   T = kpt;   NQ = N1;  NT = KPT; w = 0.5f / (BATCH * N1);  }
    else               { Q = kpt;   T = pts;   NQ = KPT; NT = N1;  w = 0.5f / (BATCH * KPT); }

    if (blockIdx.x * THREADS >= NQ && !(dir == 3 && blockIdx.x == 0)) {
        if (tid == 0) g_slots[slot] = 0.0f;
        return;
    }
    if (blockIdx.x * THREADS >= NQ + THREADS) {  // safety (unreachable)
        if (tid == 0) g_slots[slot] = 0.0f;
        return;
    }

    Q += (size_t)b * NQ * 3;
    T += (size_t)b * NT * 3;

    const int row = blockIdx.x * THREADS + tid;
    const bool valid = row < NQ;
    float qx = 0.f, qy = 0.f, qz = 0.f;
    if (valid) {
        qx = Q[row * 3 + 0];
        qy = Q[row * 3 + 1];
        qz = Q[row * 3 + 2];
    }
    const float q2  = fmaf(qx, qx, fmaf(qy, qy, qz * qz));
    const float nqx = -2.0f * qx;
    const float nqy = -2.0f * qy;
    const float nqz = -2.0f * qz;

    float m0 = 3.0e38f, m1 = 3.0e38f, m2 = 3.0e38f, m3 = 3.0e38f;

    for (int j0 = 0; j0 < NT; j0 += TILE) {
        const int j = j0 + tid;
        if (j < NT) {
            float x = T[j * 3 + 0];
            float y = T[j * 3 + 1];
            float z = T[j * 3 + 2];
            sx[tid] = x; sy[tid] = y; sz[tid] = z;
            sw[tid] = fmaf(x, x, fmaf(y, y, z * z));
        } else {
            sx[tid] = 0.f; sy[tid] = 0.f; sz[tid] = 0.f;
            sw[tid] = 3.0e38f;  // sentinel: never wins the min
        }
        __syncthreads();

        const float4* X4 = (const float4*)sx;
        const float4* Y4 = (const float4*)sy;
        const float4* Z4 = (const float4*)sz;
        const float4* W4 = (const float4*)sw;

        #pragma unroll 8
        for (int g = 0; g < TILE / 4; g++) {
            float4 X = X4[g], Y = Y4[g], Z = Z4[g], W = W4[g];
            float v0 = fmaf(X.x, nqx, fmaf(Y.x, nqy, fmaf(Z.x, nqz, W.x)));
            float v1 = fmaf(X.y, nqx, fmaf(Y.y, nqy, fmaf(Z.y, nqz, W.y)));
            float v2 = fmaf(X.z, nqx, fmaf(Y.z, nqy, fmaf(Z.z, nqz, W.z)));
            float v3 = fmaf(X.w, nqx, fmaf(Y.w, nqy, fmaf(Z.w, nqz, W.w)));
            m0 = fminf(m0, v0);
            m1 = fminf(m1, v1);
            m2 = fminf(m2, v2);
            m3 = fminf(m3, v3);
        }
        __syncthreads();
    }

    float m = fminf(fminf(m0, m1), fminf(m2, m3));
    float d2 = fmaxf(q2 + m, 0.0f);
    float v = valid ? sqrtf(d2) * w : 0.0f;

    red[tid] = v;
    __syncthreads();
    #pragma unroll
    for (int s = THREADS / 2; s > 0; s >>= 1) {
        if (tid < s) red[tid] += red[tid + s];
        __syncthreads();
    }
    if (tid == 0) g_slots[slot] = red[0];
}

__global__ void finalize_kernel(float* __restrict__ out) {
    float a = 0.0f;
    for (int i = threadIdx.x; i < 256; i += THREADS) a += g_slots[i];
    __shared__ float red[THREADS];
    red[threadIdx.x] = a;
    __syncthreads();
    #pragma unroll
    for (int s = THREADS / 2; s > 0; s >>= 1) {
        if (threadIdx.x < s) red[threadIdx.x] += red[threadIdx.x + s];
        __syncthreads();
    }
    if (threadIdx.x == 0) out[0] = red[0];
}

extern "C" void kernel_launch(void* const* d_in, const int* in_sizes, int n_in,
                              void* d_out, int out_size) {
    const float* pts         = (const float*)d_in[0];
    const float* recon_delta = (const float*)d_in[1];
    const float* kpt         = (const float*)d_in[2];
    const float* recon       = (const float*)d_in[3];
    const float* pred_nocs   = (const float*)d_in[4];
    const float* pred_R      = (const float*)d_in[5];
    const float* pred_t      = (const float*)d_in[6];
    const float* pred_s      = (const float*)d_in[7];
    const float* gt_R        = (const float*)d_in[8];
    const float* gt_t        = (const float*)d_in[9];
    const float* gt_s        = (const float*)d_in[10];

    fused_kernel<<<dim3(8, 8, 4), THREADS>>>(pts, recon, kpt, recon_delta,
                                             pred_nocs, pred_R, pred_t, pred_s,
                                             gt_R, gt_t, gt_s);
    finalize_kernel<<<1, THREADS>>>((float*)d_out);
}

// round 3
// speedup vs baseline: 1.6014x; 1.2037x over previous
#include <cuda_runtime.h>
#include <math.h>

#define BATCH 8
#define NPTS 2048
#define KPT 128
#define THREADS 256

typedef unsigned long long u64;

// ---- packed f32x2 helpers (sm_103a) ----
__device__ __forceinline__ u64 pack2(float lo, float hi) {
    u64 r;
    asm("mov.b64 %0, {%1, %2};" : "=l"(r) : "f"(lo), "f"(hi));
    return r;
}
__device__ __forceinline__ void unpack2(u64 v, float& lo, float& hi) {
    asm("mov.b64 {%0, %1}, %2;" : "=f"(lo), "=f"(hi) : "l"(v));
}
__device__ __forceinline__ u64 fma2(u64 a, u64 b, u64 c) {
    u64 d;
    asm("fma.rn.f32x2 %0, %1, %2, %3;" : "=l"(d) : "l"(a), "l"(b), "l"(c));
    return d;
}

// per-row partial min-d^2 over 4 target-quarters.
// rows: [0..16383]=dir0 (b*2048+row), [16384..32767]=dir1, [32768..33791]=dir3 (b*128+r)
__device__ float4 g_part[33792];
// slots: [0..15] dir2 item sums, [16..23] per-batch small losses
__device__ float g_slots[24];

__device__ __forceinline__ float block_reduce_256(float v, float* red) {
    const int tid = threadIdx.x;
    red[tid] = v;
    __syncthreads();
    #pragma unroll
    for (int s = THREADS / 2; s > 0; s >>= 1) {
        if (tid < s) red[tid] += red[tid + s];
        __syncthreads();
    }
    return red[0];
}

__global__ void __launch_bounds__(THREADS, 1)
passA(const float* __restrict__ pts,
      const float* __restrict__ recon,
      const float* __restrict__ kpt,
      const float* __restrict__ recon_delta,
      const float* __restrict__ pred_nocs,
      const float* __restrict__ pred_R,
      const float* __restrict__ pred_t,
      const float* __restrict__ pred_s,
      const float* __restrict__ gt_R,
      const float* __restrict__ gt_t,
      const float* __restrict__ gt_s) {
    __shared__ __align__(16) unsigned char s_buf[16384];
    __shared__ float s_red[THREADS];

    const int bid = blockIdx.x;
    const int tid = threadIdx.x;
    float* g_partf = (float*)g_part;

    if (bid < 128) {
        // ================= heavy item: dir0/dir1 chamfer quarter =================
        const int dir     = bid >> 6;
        const int b       = (bid >> 3) & 7;
        const int chunk   = (bid >> 2) & 1;
        const int quarter = bid & 3;

        const float* Q = (dir == 0 ? pts : recon) + (size_t)b * NPTS * 3;
        const float* T = (dir == 0 ? recon : pts) + (size_t)b * NPTS * 3 + quarter * 512 * 3;

        ulonglong2* A = (ulonglong2*)s_buf;        // (xx, yy) per target
        ulonglong2* B = ((ulonglong2*)s_buf) + 512; // (zz, ww) per target

        for (int j = tid; j < 512; j += THREADS) {
            float x = T[j * 3 + 0];
            float y = T[j * 3 + 1];
            float z = T[j * 3 + 2];
            float w = fmaf(x, x, fmaf(y, y, z * z));
            float nx = -2.0f * x, ny = -2.0f * y, nz = -2.0f * z;
            A[j] = make_ulonglong2(pack2(nx, nx), pack2(ny, ny));
            B[j] = make_ulonglong2(pack2(nz, nz), pack2(w, w));
        }
        __syncthreads();

        const int rowbase = chunk * 1024;
        float qx[4], qy[4], qz[4], q2[4];
        #pragma unroll
        for (int q = 0; q < 4; q++) {
            const int r = rowbase + tid + 256 * q;
            qx[q] = Q[r * 3 + 0];
            qy[q] = Q[r * 3 + 1];
            qz[q] = Q[r * 3 + 2];
            q2[q] = fmaf(qx[q], qx[q], fmaf(qy[q], qy[q], qz[q] * qz[q]));
        }
        const u64 X01 = pack2(qx[0], qx[1]), X23 = pack2(qx[2], qx[3]);
        const u64 Y01 = pack2(qy[0], qy[1]), Y23 = pack2(qy[2], qy[3]);
        const u64 Z01 = pack2(qz[0], qz[1]), Z23 = pack2(qz[2], qz[3]);

        float m0 = 3.0e38f, m1 = 3.0e38f, m2 = 3.0e38f, m3 = 3.0e38f;
        #pragma unroll 8
        for (int t = 0; t < 512; t++) {
            ulonglong2 a = A[t];
            ulonglong2 c = B[t];
            u64 vA = fma2(a.x, X01, fma2(a.y, Y01, fma2(c.x, Z01, c.y)));
            u64 vB = fma2(a.x, X23, fma2(a.y, Y23, fma2(c.x, Z23, c.y)));
            float l, h;
            unpack2(vA, l, h);
            m0 = fminf(m0, l);
            m1 = fminf(m1, h);
            unpack2(vB, l, h);
            m2 = fminf(m2, l);
            m3 = fminf(m3, h);
        }

        const int prow = dir * 16384 + b * 2048 + rowbase + tid;
        g_partf[(prow        ) * 4 + quarter] = q2[0] + m0;
        g_partf[(prow +  256 ) * 4 + quarter] = q2[1] + m1;
        g_partf[(prow +  512 ) * 4 + quarter] = q2[2] + m2;
        g_partf[(prow +  768 ) * 4 + quarter] = q2[3] + m3;
        return;
    }

    // ================= light items: blocks 128..147 loop over ids =================
    for (int id = bid - 128; id < 56; id += 20) {
        __syncthreads();  // protect s_buf reuse across items

        if (id < 16) {
            // ---- dir2: pts -> kpt, full 128 targets, direct sum ----
            const int b = id >> 1;
            const int half = id & 1;
            const float* Q = pts + (size_t)b * NPTS * 3;
            const float* T = kpt + (size_t)b * KPT * 3;
            float4* tile = (float4*)s_buf;
            if (tid < KPT) {
                float x = T[tid * 3 + 0];
                float y = T[tid * 3 + 1];
                float z = T[tid * 3 + 2];
                float w = fmaf(x, x, fmaf(y, y, z * z));
                tile[tid] = make_float4(-2.0f * x, -2.0f * y, -2.0f * z, w);
            }
            __syncthreads();

            const int rowbase = half * 1024;
            float sum = 0.0f;
            #pragma unroll
            for (int q = 0; q < 4; q++) {
                const int r = rowbase + tid + 256 * q;
                float qx = Q[r * 3 + 0];
                float qy = Q[r * 3 + 1];
                float qz = Q[r * 3 + 2];
                float q2 = fmaf(qx, qx, fmaf(qy, qy, qz * qz));
                float m = 3.0e38f;
                #pragma unroll 8
                for (int t = 0; t < KPT; t++) {
                    float4 s = tile[t];
                    float v = fmaf(s.x, qx, fmaf(s.y, qy, fmaf(s.z, qz, s.w)));
                    m = fminf(m, v);
                }
                sum += sqrtf(fmaxf(q2 + m, 0.0f));
            }
            float tot = block_reduce_256(sum, s_red);
            if (tid == 0) g_slots[id] = tot * (0.5f / (BATCH * NPTS));
        } else if (id < 48) {
            // ---- dir3: kpt -> pts, 128 queries, 512-target quarter -> partial ----
            const int j = id - 16;
            const int b = j >> 2;
            const int quarter = j & 3;
            const float* Q = kpt + (size_t)b * KPT * 3;
            const float* T = pts + (size_t)b * NPTS * 3 + quarter * 512 * 3;
            float4* tile = (float4*)s_buf;
            for (int jj = tid; jj < 512; jj += THREADS) {
                float x = T[jj * 3 + 0];
                float y = T[jj * 3 + 1];
                float z = T[jj * 3 + 2];
                float w = fmaf(x, x, fmaf(y, y, z * z));
                tile[jj] = make_float4(-2.0f * x, -2.0f * y, -2.0f * z, w);
            }
            __syncthreads();

            if (tid < KPT) {
                float qx = Q[tid * 3 + 0];
                float qy = Q[tid * 3 + 1];
                float qz = Q[tid * 3 + 2];
                float q2 = fmaf(qx, qx, fmaf(qy, qy, qz * qz));
                float m = 3.0e38f;
                #pragma unroll 8
                for (int t = 0; t < 512; t++) {
                    float4 s = tile[t];
                    float v = fmaf(s.x, qx, fmaf(s.y, qy, fmaf(s.z, qz, s.w)));
                    m = fminf(m, v);
                }
                g_partf[(32768 + b * KPT + tid) * 4 + quarter] = q2 + m;
            }
        } else {
            // ---- smalls: pose + NOCS + diversity + delta, per batch ----
            const int b = id - 48;
            float* sk = (float*)s_buf;
            const float* K = kpt + (size_t)b * KPT * 3;
            for (int i = tid; i < KPT * 3; i += THREADS) sk[i] = K[i];
            __syncthreads();

            float acc = 0.0f;
            const float invDiv = 1.0f / (float)(BATCH * KPT * KPT);
            for (int p = tid; p < KPT * KPT; p += THREADS) {
                const int i = p >> 7;
                const int jj = p & 127;
                float c;
                if (i == jj) {
                    c = 0.1f;
                } else {
                    float dx = sk[i * 3 + 0] - sk[jj * 3 + 0];
                    float dy = sk[i * 3 + 1] - sk[jj * 3 + 1];
                    float dz = sk[i * 3 + 2] - sk[jj * 3 + 2];
                    c = fminf(sqrtf(fmaf(dx, dx, fmaf(dy, dy, dz * dz))), 0.1f);
                }
                acc += c * invDiv;
            }

            if (tid < KPT) {
                const float* R = gt_R + (size_t)b * 9;
                const float t0 = gt_t[b * 3 + 0], t1 = gt_t[b * 3 + 1], t2 = gt_t[b * 3 + 2];
                const float s0 = gt_s[b * 3 + 0], s1 = gt_s[b * 3 + 1], s2 = gt_s[b * 3 + 2];
                const float scale = sqrtf(s0 * s0 + s1 * s1 + s2 * s2) + 1e-8f;
                const float inv = 1.0f / scale;
                const float px = (sk[tid * 3 + 0] - t0) * inv;
                const float py = (sk[tid * 3 + 1] - t1) * inv;
                const float pz = (sk[tid * 3 + 2] - t2) * inv;
                const float* pn = pred_nocs + ((size_t)b * KPT + tid) * 3;
                float sl = 0.0f;
                #pragma unroll
                for (int jj = 0; jj < 3; jj++) {
                    float g = px * R[jj] + py * R[3 + jj] + pz * R[6 + jj];
                    float d = fabsf(pn[jj] - g);
                    sl += (d > 0.1f) ? (d - 0.05f) : (d * d * 5.0f);
                }
                acc += sl * (1.0f / (float)(BATCH * KPT));
            }

            const float* D = recon_delta + (size_t)b * NPTS * 3;
            float dsum = 0.0f;
            for (int r = tid; r < NPTS; r += THREADS) {
                float x = D[r * 3 + 0];
                float y = D[r * 3 + 1];
                float z = D[r * 3 + 2];
                dsum += sqrtf(fmaf(x, x, fmaf(y, y, z * z)));
            }
            acc += dsum * (1.0f / (float)(BATCH * NPTS));

            float tot = block_reduce_256(acc, s_red);
            if (tid == 0) {
                const float* Rp = pred_R + (size_t)b * 9;
                const float* Rg = gt_R + (size_t)b * 9;
                float cs = 0.0f;
                #pragma unroll
                for (int jj = 0; jj < 3; jj++) {
                    float a0 = Rp[jj]     - Rg[jj];
                    float a1 = Rp[3 + jj] - Rg[3 + jj];
                    float a2 = Rp[6 + jj] - Rg[6 + jj];
                    cs += sqrtf(a0 * a0 + a1 * a1 + a2 * a2);
                }
                float dt0 = pred_t[b * 3 + 0] - gt_t[b * 3 + 0];
                float dt1 = pred_t[b * 3 + 1] - gt_t[b * 3 + 1];
                float dt2 = pred_t[b * 3 + 2] - gt_t[b * 3 + 2];
                float tn = sqrtf(dt0 * dt0 + dt1 * dt1 + dt2 * dt2);
                float ds0 = pred_s[b * 3 + 0] - gt_s[b * 3 + 0];
                float ds1 = pred_s[b * 3 + 1] - gt_s[b * 3 + 1];
                float ds2 = pred_s[b * 3 + 2] - gt_s[b * 3 + 2];
                float sn = sqrtf(ds0 * ds0 + ds1 * ds1 + ds2 * ds2);
                g_slots[16 + b] = tot
                                + cs * (1.0f / (3.0f * BATCH))
                                + tn * (1.0f / BATCH)
                                + sn * (1.0f / BATCH);
            }
        }
    }
}

__global__ void pass2(float* __restrict__ out) {
    const int tid = threadIdx.x;  // 1024 threads
    float a = 0.0f;
    // dir0 + dir1 rows (weight equal: 0.5/(B*2048) each direction)
    for (int i = tid; i < 32768; i += 1024) {
        float4 p = g_part[i];
        float m = fminf(fminf(p.x, p.y), fminf(p.z, p.w));
        a += sqrtf(fmaxf(m, 0.0f));
    }
    a *= 0.5f / (BATCH * NPTS);
    // dir3 rows
    {
        float4 p = g_part[32768 + tid];
        float m = fminf(fminf(p.x, p.y), fminf(p.z, p.w));
        a += sqrtf(fmaxf(m, 0.0f)) * (0.5f / (BATCH * KPT));
    }
    if (tid < 24) a += g_slots[tid];

    __shared__ float red[1024];
    red[tid] = a;
    __syncthreads();
    #pragma unroll
    for (int s = 512; s > 0; s >>= 1) {
        if (tid < s) red[tid] += red[tid + s];
        __syncthreads();
    }
    if (tid == 0) out[0] = red[0];
}

extern "C" void kernel_launch(void* const* d_in, const int* in_sizes, int n_in,
                              void* d_out, int out_size) {
    const float* pts         = (const float*)d_in[0];
    const float* recon_delta = (const float*)d_in[1];
    const float* kpt         = (const float*)d_in[2];
    const float* recon       = (const float*)d_in[3];
    const float* pred_nocs   = (const float*)d_in[4];
    const float* pred_R      = (const float*)d_in[5];
    const float* pred_t      = (const float*)d_in[6];
    const float* pred_s      = (const float*)d_in[7];
    const float* gt_R        = (const float*)d_in[8];
    const float* gt_t        = (const float*)d_in[9];
    const float* gt_s        = (const float*)d_in[10];

    passA<<<148, THREADS>>>(pts, recon, kpt, recon_delta, pred_nocs,
                            pred_R, pred_t, pred_s, gt_R, gt_t, gt_s);
    pass2<<<1, 1024>>>((float*)d_out);
}

// round 4
// speedup vs baseline: 1.8393x; 1.1485x over previous
#include <cuda_runtime.h>
#include <math.h>

#define BATCH 8
#define NPTS 2048
#define KPT 128
#define THREADS 256

typedef unsigned long long u64;

__device__ __forceinline__ u64 pack2(float lo, float hi) {
    u64 r;
    asm("mov.b64 %0, {%1, %2};" : "=l"(r) : "f"(lo), "f"(hi));
    return r;
}
__device__ __forceinline__ void unpack2(u64 v, float& lo, float& hi) {
    asm("mov.b64 {%0, %1}, %2;" : "=f"(lo), "=f"(hi) : "l"(v));
}
__device__ __forceinline__ u64 fma2(u64 a, u64 b, u64 c) {
    u64 d;
    asm("fma.rn.f32x2 %0, %1, %2, %3;" : "=l"(d) : "l"(a), "l"(b), "l"(c));
    return d;
}

// dir0/dir1 partial min-d^2, transposed: g_part8[eighth][dir*16384 + b*2048 + row]
__device__ float g_part8[8 * 32768];
// dir3 partials: g_d3[quarter][b*128 + r]
__device__ float g_d3[4 * 1024];
// slots: [0..15] dir2 item sums, [16..23] per-batch small losses
__device__ float g_slots[24];
// per-block sums from pass2
__device__ float g_bsum[129];

__device__ __forceinline__ float block_reduce_256(float v, float* red) {
    const int tid = threadIdx.x;
    red[tid] = v;
    __syncthreads();
    #pragma unroll
    for (int s = THREADS / 2; s > 0; s >>= 1) {
        if (tid < s) red[tid] += red[tid + s];
        __syncthreads();
    }
    return red[0];
}

__global__ void __launch_bounds__(THREADS, 1)
passA(const float* __restrict__ pts,
      const float* __restrict__ recon,
      const float* __restrict__ kpt,
      const float* __restrict__ recon_delta,
      const float* __restrict__ pred_nocs,
      const float* __restrict__ pred_R,
      const float* __restrict__ pred_t,
      const float* __restrict__ pred_s,
      const float* __restrict__ gt_R,
      const float* __restrict__ gt_t,
      const float* __restrict__ gt_s) {
    __shared__ __align__(16) unsigned char s_buf[8192];
    __shared__ float s_red[THREADS];

    const int bid = blockIdx.x;
    const int tid = threadIdx.x;

    if (bid < 128) {
        // ===== heavy: dir0/dir1, all 2048 rows (8/thread), 256-target eighth =====
        const int dir = bid >> 6;
        const int b   = (bid >> 3) & 7;
        const int e   = bid & 7;

        const float* Q = (dir == 0 ? pts : recon) + (size_t)b * NPTS * 3;
        const float* T = (dir == 0 ? recon : pts) + (size_t)b * NPTS * 3 + e * 256 * 3;

        float4* tile = (float4*)s_buf;  // (-2x, -2y, -2z, |s|^2) per target
        {
            float x = T[tid * 3 + 0];
            float y = T[tid * 3 + 1];
            float z = T[tid * 3 + 2];
            float w = fmaf(x, x, fmaf(y, y, z * z));
            tile[tid] = make_float4(-2.0f * x, -2.0f * y, -2.0f * z, w);
        }
        __syncthreads();

        float qx[8], qy[8], qz[8], q2[8];
        #pragma unroll
        for (int q = 0; q < 8; q++) {
            const int r = tid + 256 * q;
            qx[q] = Q[r * 3 + 0];
            qy[q] = Q[r * 3 + 1];
            qz[q] = Q[r * 3 + 2];
            q2[q] = fmaf(qx[q], qx[q], fmaf(qy[q], qy[q], qz[q] * qz[q]));
        }
        u64 X[4], Y[4], Z[4];
        #pragma unroll
        for (int q = 0; q < 4; q++) {
            X[q] = pack2(qx[2 * q], qx[2 * q + 1]);
            Y[q] = pack2(qy[2 * q], qy[2 * q + 1]);
            Z[q] = pack2(qz[2 * q], qz[2 * q + 1]);
        }

        float m[8];
        #pragma unroll
        for (int q = 0; q < 8; q++) m[q] = 3.0e38f;

        #pragma unroll 4
        for (int t = 0; t < 256; t++) {
            float4 s = tile[t];
            u64 ax = pack2(s.x, s.x);
            u64 ay = pack2(s.y, s.y);
            u64 az = pack2(s.z, s.z);
            u64 aw = pack2(s.w, s.w);
            #pragma unroll
            for (int q = 0; q < 4; q++) {
                u64 v = fma2(ax, X[q], fma2(ay, Y[q], fma2(az, Z[q], aw)));
                float lo, hi;
                unpack2(v, lo, hi);
                m[2 * q]     = fminf(m[2 * q], lo);
                m[2 * q + 1] = fminf(m[2 * q + 1], hi);
            }
        }

        const int rowbase = dir * 16384 + b * 2048;
        float* dst = g_part8 + (size_t)e * 32768 + rowbase;
        #pragma unroll
        for (int q = 0; q < 8; q++) dst[tid + 256 * q] = q2[q] + m[q];
        return;
    }

    // ===== light items on blocks 128..147 =====
    for (int id = bid - 128; id < 56; id += 20) {
        __syncthreads();

        if (id < 16) {
            // dir2: pts -> kpt, 1024-row half, full 128 targets
            const int b = id >> 1;
            const int half = id & 1;
            const float* Q = pts + (size_t)b * NPTS * 3;
            const float* T = kpt + (size_t)b * KPT * 3;
            float4* tile = (float4*)s_buf;
            if (tid < KPT) {
                float x = T[tid * 3 + 0];
                float y = T[tid * 3 + 1];
                float z = T[tid * 3 + 2];
                float w = fmaf(x, x, fmaf(y, y, z * z));
                tile[tid] = make_float4(-2.0f * x, -2.0f * y, -2.0f * z, w);
            }
            __syncthreads();

            const int rowbase = half * 1024;
            float sum = 0.0f;
            #pragma unroll
            for (int q = 0; q < 4; q++) {
                const int r = rowbase + tid + 256 * q;
                float qx = Q[r * 3 + 0];
                float qy = Q[r * 3 + 1];
                float qz = Q[r * 3 + 2];
                float q2 = fmaf(qx, qx, fmaf(qy, qy, qz * qz));
                float mm = 3.0e38f;
                #pragma unroll 8
                for (int t = 0; t < KPT; t++) {
                    float4 s = tile[t];
                    float v = fmaf(s.x, qx, fmaf(s.y, qy, fmaf(s.z, qz, s.w)));
                    mm = fminf(mm, v);
                }
                sum += sqrtf(fmaxf(q2 + mm, 0.0f));
            }
            float tot = block_reduce_256(sum, s_red);
            if (tid == 0) g_slots[id] = tot * (0.5f / (BATCH * NPTS));
        } else if (id < 48) {
            // dir3: kpt -> pts, 512-target quarter -> partial
            const int j = id - 16;
            const int b = j >> 2;
            const int quarter = j & 3;
            const float* Q = kpt + (size_t)b * KPT * 3;
            const float* T = pts + (size_t)b * NPTS * 3 + quarter * 512 * 3;
            float4* tile = (float4*)s_buf;
            for (int jj = tid; jj < 512; jj += THREADS) {
                float x = T[jj * 3 + 0];
                float y = T[jj * 3 + 1];
                float z = T[jj * 3 + 2];
                float w = fmaf(x, x, fmaf(y, y, z * z));
                tile[jj] = make_float4(-2.0f * x, -2.0f * y, -2.0f * z, w);
            }
            __syncthreads();

            if (tid < KPT) {
                float qx = Q[tid * 3 + 0];
                float qy = Q[tid * 3 + 1];
                float qz = Q[tid * 3 + 2];
                float q2 = fmaf(qx, qx, fmaf(qy, qy, qz * qz));
                float mm = 3.0e38f;
                #pragma unroll 8
                for (int t = 0; t < 512; t++) {
                    float4 s = tile[t];
                    float v = fmaf(s.x, qx, fmaf(s.y, qy, fmaf(s.z, qz, s.w)));
                    mm = fminf(mm, v);
                }
                g_d3[quarter * 1024 + b * KPT + tid] = q2 + mm;
            }
        } else {
            // smalls: pose + NOCS + diversity + delta per batch
            const int b = id - 48;
            float* sk = (float*)s_buf;
            const float* K = kpt + (size_t)b * KPT * 3;
            for (int i = tid; i < KPT * 3; i += THREADS) sk[i] = K[i];
            __syncthreads();

            float acc = 0.0f;
            const float invDiv = 1.0f / (float)(BATCH * KPT * KPT);
            for (int p = tid; p < KPT * KPT; p += THREADS) {
                const int i = p >> 7;
                const int jj = p & 127;
                float c;
                if (i == jj) {
                    c = 0.1f;
                } else {
                    float dx = sk[i * 3 + 0] - sk[jj * 3 + 0];
                    float dy = sk[i * 3 + 1] - sk[jj * 3 + 1];
                    float dz = sk[i * 3 + 2] - sk[jj * 3 + 2];
                    c = fminf(sqrtf(fmaf(dx, dx, fmaf(dy, dy, dz * dz))), 0.1f);
                }
                acc += c * invDiv;
            }

            if (tid < KPT) {
                const float* R = gt_R + (size_t)b * 9;
                const float t0 = gt_t[b * 3 + 0], t1 = gt_t[b * 3 + 1], t2 = gt_t[b * 3 + 2];
                const float s0 = gt_s[b * 3 + 0], s1 = gt_s[b * 3 + 1], s2 = gt_s[b * 3 + 2];
                const float scale = sqrtf(s0 * s0 + s1 * s1 + s2 * s2) + 1e-8f;
                const float inv = 1.0f / scale;
                const float px = (sk[tid * 3 + 0] - t0) * inv;
                const float py = (sk[tid * 3 + 1] - t1) * inv;
                const float pz = (sk[tid * 3 + 2] - t2) * inv;
                const float* pn = pred_nocs + ((size_t)b * KPT + tid) * 3;
                float sl = 0.0f;
                #pragma unroll
                for (int jj = 0; jj < 3; jj++) {
                    float g = px * R[jj] + py * R[3 + jj] + pz * R[6 + jj];
                    float d = fabsf(pn[jj] - g);
                    sl += (d > 0.1f) ? (d - 0.05f) : (d * d * 5.0f);
                }
                acc += sl * (1.0f / (float)(BATCH * KPT));
            }

            const float* D = recon_delta + (size_t)b * NPTS * 3;
            float dsum = 0.0f;
            for (int r = tid; r < NPTS; r += THREADS) {
                float x = D[r * 3 + 0];
                float y = D[r * 3 + 1];
                float z = D[r * 3 + 2];
                dsum += sqrtf(fmaf(x, x, fmaf(y, y, z * z)));
            }
            acc += dsum * (1.0f / (float)(BATCH * NPTS));

            float tot = block_reduce_256(acc, s_red);
            if (tid == 0) {
                const float* Rp = pred_R + (size_t)b * 9;
                const float* Rg = gt_R + (size_t)b * 9;
                float cs = 0.0f;
                #pragma unroll
                for (int jj = 0; jj < 3; jj++) {
                    float a0 = Rp[jj]     - Rg[jj];
                    float a1 = Rp[3 + jj] - Rg[3 + jj];
                    float a2 = Rp[6 + jj] - Rg[6 + jj];
                    cs += sqrtf(a0 * a0 + a1 * a1 + a2 * a2);
                }
                float dt0 = pred_t[b * 3 + 0] - gt_t[b * 3 + 0];
                float dt1 = pred_t[b * 3 + 1] - gt_t[b * 3 + 1];
                float dt2 = pred_t[b * 3 + 2] - gt_t[b * 3 + 2];
                float tn = sqrtf(dt0 * dt0 + dt1 * dt1 + dt2 * dt2);
                float ds0 = pred_s[b * 3 + 0] - gt_s[b * 3 + 0];
                float ds1 = pred_s[b * 3 + 1] - gt_s[b * 3 + 1];
                float ds2 = pred_s[b * 3 + 2] - gt_s[b * 3 + 2];
                float sn = sqrtf(ds0 * ds0 + ds1 * ds1 + ds2 * ds2);
                g_slots[16 + b] = tot
                                + cs * (1.0f / (3.0f * BATCH))
                                + tn * (1.0f / BATCH)
                                + sn * (1.0f / BATCH);
            }
        }
    }
}

__global__ void pass2() {
    __shared__ float red[THREADS];
    const int bid = blockIdx.x;
    const int tid = threadIdx.x;
    float a = 0.0f;

    if (bid < 128) {
        const int row = bid * 256 + tid;
        float mm = 3.0e38f;
        #pragma unroll
        for (int e = 0; e < 8; e++) mm = fminf(mm, g_part8[e * 32768 + row]);
        a = sqrtf(fmaxf(mm, 0.0f)) * (0.5f / (BATCH * NPTS));
    } else {
        // dir3 rows (1024) at 4/thread + slots
        #pragma unroll
        for (int q = 0; q < 4; q++) {
            const int idx = tid + 256 * q;
            float mm = fminf(fminf(g_d3[idx], g_d3[1024 + idx]),
                             fminf(g_d3[2048 + idx], g_d3[3072 + idx]));
            a += sqrtf(fmaxf(mm, 0.0f)) * (0.5f / (BATCH * KPT));
        }
        if (tid < 24) a += g_slots[tid];
    }

    red[tid] = a;
    __syncthreads();
    #pragma unroll
    for (int s = THREADS / 2; s > 0; s >>= 1) {
        if (tid < s) red[tid] += red[tid + s];
        __syncthreads();
    }
    if (tid == 0) g_bsum[bid] = red[0];
}

__global__ void pass3(float* __restrict__ out) {
    const int tid = threadIdx.x;
    float a = (tid < 129) ? g_bsum[tid] : 0.0f;
    __shared__ float red[THREADS];
    red[tid] = a;
    __syncthreads();
    #pragma unroll
    for (int s = THREADS / 2; s > 0; s >>= 1) {
        if (tid < s) red[tid] += red[tid + s];
        __syncthreads();
    }
    if (tid == 0) out[0] = red[0];
}

extern "C" void kernel_launch(void* const* d_in, const int* in_sizes, int n_in,
                              void* d_out, int out_size) {
    const float* pts         = (const float*)d_in[0];
    const float* recon_delta = (const float*)d_in[1];
    const float* kpt         = (const float*)d_in[2];
    const float* recon       = (const float*)d_in[3];
    const float* pred_nocs   = (const float*)d_in[4];
    const float* pred_R      = (const float*)d_in[5];
    const float* pred_t      = (const float*)d_in[6];
    const float* pred_s      = (const float*)d_in[7];
    const float* gt_R        = (const float*)d_in[8];
    const float* gt_t        = (const float*)d_in[9];
    const float* gt_s        = (const float*)d_in[10];

    passA<<<148, THREADS>>>(pts, recon, kpt, recon_delta, pred_nocs,
                            pred_R, pred_t, pred_s, gt_R, gt_t, gt_s);
    pass2<<<129, THREADS>>>();
    pass3<<<1, THREADS>>>((float*)d_out);
}

// round 5
// speedup vs baseline: 1.9652x; 1.0685x over previous
#include <cuda_runtime.h>
#include <math.h>

#define BATCH 8
#define NPTS 2048
#define KPT 128
#define THREADS 256

typedef unsigned long long u64;

__device__ __forceinline__ u64 pack2(float lo, float hi) {
    u64 r;
    asm("mov.b64 %0, {%1, %2};" : "=l"(r) : "f"(lo), "f"(hi));
    return r;
}
__device__ __forceinline__ void unpack2(u64 v, float& lo, float& hi) {
    asm("mov.b64 {%0, %1}, %2;" : "=f"(lo), "=f"(hi) : "l"(v));
}
__device__ __forceinline__ u64 fma2(u64 a, u64 b, u64 c) {
    u64 d;
    asm("fma.rn.f32x2 %0, %1, %2, %3;" : "=l"(d) : "l"(a), "l"(b), "l"(c));
    return d;
}

// dir0/dir1 partial min-d^2: g_part16[sixteenth][dir*16384 + b*2048 + row]
__device__ float g_part16[16 * 32768];
// dir3 partials: g_d3[quarter][b*128 + r]
__device__ float g_d3[4 * 1024];
// slots: [0..15] dir2 item sums, [16..23] per-batch small losses
__device__ float g_slots[24];
// per-block sums from pass2
__device__ float g_bsum[129];

__device__ __forceinline__ float block_reduce_256(float v, float* red) {
    const int tid = threadIdx.x;
    red[tid] = v;
    __syncthreads();
    #pragma unroll
    for (int s = THREADS / 2; s > 0; s >>= 1) {
        if (tid < s) red[tid] += red[tid + s];
        __syncthreads();
    }
    return red[0];
}

__global__ void __launch_bounds__(THREADS, 2)
passA(const float* __restrict__ pts,
      const float* __restrict__ recon,
      const float* __restrict__ kpt,
      const float* __restrict__ recon_delta,
      const float* __restrict__ pred_nocs,
      const float* __restrict__ pred_R,
      const float* __restrict__ pred_t,
      const float* __restrict__ pred_s,
      const float* __restrict__ gt_R,
      const float* __restrict__ gt_t,
      const float* __restrict__ gt_s) {
    __shared__ __align__(16) unsigned char s_buf[8192];
    __shared__ float s_red[THREADS];

    const int bid = blockIdx.x;
    const int tid = threadIdx.x;

    if (bid < 256) {
        // ===== heavy: dir0/dir1, 2048 rows (8/thread), 128-target sixteenth =====
        const int dir = bid >> 7;
        const int b   = (bid >> 4) & 7;
        const int s16 = bid & 15;

        const float* Q = (dir == 0 ? pts : recon) + (size_t)b * NPTS * 3;
        const float* T = (dir == 0 ? recon : pts) + (size_t)b * NPTS * 3 + s16 * 128 * 3;

        // tile: target-pair packed arrays, each 128 floats (=64 u64 pairs)
        float* txf = (float*)s_buf;
        float* tyf = txf + 128;
        float* tzf = tyf + 128;
        float* twf = tzf + 128;
        if (tid < 128) {
            float x = T[tid * 3 + 0];
            float y = T[tid * 3 + 1];
            float z = T[tid * 3 + 2];
            txf[tid] = -2.0f * x;
            tyf[tid] = -2.0f * y;
            tzf[tid] = -2.0f * z;
            twf[tid] = fmaf(x, x, fmaf(y, y, z * z));
        }
        __syncthreads();

        // 8 query rows per thread, duplicated into f32x2 registers (hoisted)
        u64 X[8], Y[8], Z[8];
        float q2[8];
        #pragma unroll
        for (int q = 0; q < 8; q++) {
            const int r = tid + 256 * q;
            float qx = Q[r * 3 + 0];
            float qy = Q[r * 3 + 1];
            float qz = Q[r * 3 + 2];
            q2[q] = fmaf(qx, qx, fmaf(qy, qy, qz * qz));
            X[q] = pack2(qx, qx);
            Y[q] = pack2(qy, qy);
            Z[q] = pack2(qz, qz);
        }

        float m[8];
        #pragma unroll
        for (int q = 0; q < 8; q++) m[q] = 3.0e38f;

        const ulonglong2* TX = (const ulonglong2*)txf;  // 2 target-pairs = 4 targets
        const ulonglong2* TY = (const ulonglong2*)tyf;
        const ulonglong2* TZ = (const ulonglong2*)tzf;
        const ulonglong2* TW = (const ulonglong2*)twf;

        #pragma unroll 2
        for (int p = 0; p < 32; p++) {
            ulonglong2 ax = TX[p], ay = TY[p], az = TZ[p], aw = TW[p];
            #pragma unroll
            for (int q = 0; q < 8; q++) {
                u64 v0 = fma2(ax.x, X[q], fma2(ay.x, Y[q], fma2(az.x, Z[q], aw.x)));
                u64 v1 = fma2(ax.y, X[q], fma2(ay.y, Y[q], fma2(az.y, Z[q], aw.y)));
                float a, bb, c, d;
                unpack2(v0, a, bb);
                unpack2(v1, c, d);
                m[q] = fminf(fminf(m[q], fminf(a, bb)), fminf(c, d));
            }
        }

        float* dst = g_part16 + (size_t)s16 * 32768 + dir * 16384 + b * 2048;
        #pragma unroll
        for (int q = 0; q < 8; q++) dst[tid + 256 * q] = q2[q] + m[q];
        return;
    }

    // ===== light items on blocks 256..295 =====
    for (int id = bid - 256; id < 56; id += 40) {
        __syncthreads();

        if (id < 16) {
            // dir2: pts -> kpt, 1024-row half, full 128 targets
            const int b = id >> 1;
            const int half = id & 1;
            const float* Q = pts + (size_t)b * NPTS * 3;
            const float* T = kpt + (size_t)b * KPT * 3;
            float4* tile = (float4*)s_buf;
            if (tid < KPT) {
                float x = T[tid * 3 + 0];
                float y = T[tid * 3 + 1];
                float z = T[tid * 3 + 2];
                float w = fmaf(x, x, fmaf(y, y, z * z));
                tile[tid] = make_float4(-2.0f * x, -2.0f * y, -2.0f * z, w);
            }
            __syncthreads();

            const int rowbase = half * 1024;
            float sum = 0.0f;
            #pragma unroll
            for (int q = 0; q < 4; q++) {
                const int r = rowbase + tid + 256 * q;
                float qx = Q[r * 3 + 0];
                float qy = Q[r * 3 + 1];
                float qz = Q[r * 3 + 2];
                float q2 = fmaf(qx, qx, fmaf(qy, qy, qz * qz));
                float mm = 3.0e38f;
                #pragma unroll 8
                for (int t = 0; t < KPT; t++) {
                    float4 s = tile[t];
                    float v = fmaf(s.x, qx, fmaf(s.y, qy, fmaf(s.z, qz, s.w)));
                    mm = fminf(mm, v);
                }
                sum += sqrtf(fmaxf(q2 + mm, 0.0f));
            }
            float tot = block_reduce_256(sum, s_red);
            if (tid == 0) g_slots[id] = tot * (0.5f / (BATCH * NPTS));
        } else if (id < 48) {
            // dir3: kpt -> pts, 512-target quarter -> partial
            const int j = id - 16;
            const int b = j >> 2;
            const int quarter = j & 3;
            const float* Q = kpt + (size_t)b * KPT * 3;
            const float* T = pts + (size_t)b * NPTS * 3 + quarter * 512 * 3;
            float4* tile = (float4*)s_buf;
            for (int jj = tid; jj < 512; jj += THREADS) {
                float x = T[jj * 3 + 0];
                float y = T[jj * 3 + 1];
                float z = T[jj * 3 + 2];
                float w = fmaf(x, x, fmaf(y, y, z * z));
                tile[jj] = make_float4(-2.0f * x, -2.0f * y, -2.0f * z, w);
            }
            __syncthreads();

            if (tid < KPT) {
                float qx = Q[tid * 3 + 0];
                float qy = Q[tid * 3 + 1];
                float qz = Q[tid * 3 + 2];
                float q2 = fmaf(qx, qx, fmaf(qy, qy, qz * qz));
                float mm = 3.0e38f;
                #pragma unroll 8
                for (int t = 0; t < 512; t++) {
                    float4 s = tile[t];
                    float v = fmaf(s.x, qx, fmaf(s.y, qy, fmaf(s.z, qz, s.w)));
                    mm = fminf(mm, v);
                }
                g_d3[quarter * 1024 + b * KPT + tid] = q2 + mm;
            }
        } else {
            // smalls: pose + NOCS + diversity + delta per batch
            const int b = id - 48;
            float* sk = (float*)s_buf;
            const float* K = kpt + (size_t)b * KPT * 3;
            for (int i = tid; i < KPT * 3; i += THREADS) sk[i] = K[i];
            __syncthreads();

            float acc = 0.0f;
            const float invDiv = 1.0f / (float)(BATCH * KPT * KPT);
            for (int p = tid; p < KPT * KPT; p += THREADS) {
                const int i = p >> 7;
                const int jj = p & 127;
                float c;
                if (i == jj) {
                    c = 0.1f;
                } else {
                    float dx = sk[i * 3 + 0] - sk[jj * 3 + 0];
                    float dy = sk[i * 3 + 1] - sk[jj * 3 + 1];
                    float dz = sk[i * 3 + 2] - sk[jj * 3 + 2];
                    c = fminf(sqrtf(fmaf(dx, dx, fmaf(dy, dy, dz * dz))), 0.1f);
                }
                acc += c * invDiv;
            }

            if (tid < KPT) {
                const float* R = gt_R + (size_t)b * 9;
                const float t0 = gt_t[b * 3 + 0], t1 = gt_t[b * 3 + 1], t2 = gt_t[b * 3 + 2];
                const float s0 = gt_s[b * 3 + 0], s1 = gt_s[b * 3 + 1], s2 = gt_s[b * 3 + 2];
                const float scale = sqrtf(s0 * s0 + s1 * s1 + s2 * s2) + 1e-8f;
                const float inv = 1.0f / scale;
                const float px = (sk[tid * 3 + 0] - t0) * inv;
                const float py = (sk[tid * 3 + 1] - t1) * inv;
                const float pz = (sk[tid * 3 + 2] - t2) * inv;
                const float* pn = pred_nocs + ((size_t)b * KPT + tid) * 3;
                float sl = 0.0f;
                #pragma unroll
                for (int jj = 0; jj < 3; jj++) {
                    float g = px * R[jj] + py * R[3 + jj] + pz * R[6 + jj];
                    float d = fabsf(pn[jj] - g);
                    sl += (d > 0.1f) ? (d - 0.05f) : (d * d * 5.0f);
                }
                acc += sl * (1.0f / (float)(BATCH * KPT));
            }

            const float* D = recon_delta + (size_t)b * NPTS * 3;
            float dsum = 0.0f;
            for (int r = tid; r < NPTS; r += THREADS) {
                float x = D[r * 3 + 0];
                float y = D[r * 3 + 1];
                float z = D[r * 3 + 2];
                dsum += sqrtf(fmaf(x, x, fmaf(y, y, z * z)));
            }
            acc += dsum * (1.0f / (float)(BATCH * NPTS));

            float tot = block_reduce_256(acc, s_red);
            if (tid == 0) {
                const float* Rp = pred_R + (size_t)b * 9;
                const float* Rg = gt_R + (size_t)b * 9;
                float cs = 0.0f;
                #pragma unroll
                for (int jj = 0; jj < 3; jj++) {
                    float a0 = Rp[jj]     - Rg[jj];
                    float a1 = Rp[3 + jj] - Rg[3 + jj];
                    float a2 = Rp[6 + jj] - Rg[6 + jj];
                    cs += sqrtf(a0 * a0 + a1 * a1 + a2 * a2);
                }
                float dt0 = pred_t[b * 3 + 0] - gt_t[b * 3 + 0];
                float dt1 = pred_t[b * 3 + 1] - gt_t[b * 3 + 1];
                float dt2 = pred_t[b * 3 + 2] - gt_t[b * 3 + 2];
                float tn = sqrtf(dt0 * dt0 + dt1 * dt1 + dt2 * dt2);
                float ds0 = pred_s[b * 3 + 0] - gt_s[b * 3 + 0];
                float ds1 = pred_s[b * 3 + 1] - gt_s[b * 3 + 1];
                float ds2 = pred_s[b * 3 + 2] - gt_s[b * 3 + 2];
                float sn = sqrtf(ds0 * ds0 + ds1 * ds1 + ds2 * ds2);
                g_slots[16 + b] = tot
                                + cs * (1.0f / (3.0f * BATCH))
                                + tn * (1.0f / BATCH)
                                + sn * (1.0f / BATCH);
            }
        }
    }
}

__global__ void pass2() {
    __shared__ float red[THREADS];
    const int bid = blockIdx.x;
    const int tid = threadIdx.x;
    float a = 0.0f;

    if (bid < 128) {
        const int row = bid * 256 + tid;
        float mm = 3.0e38f;
        #pragma unroll
        for (int e = 0; e < 16; e++) mm = fminf(mm, g_part16[e * 32768 + row]);
        a = sqrtf(fmaxf(mm, 0.0f)) * (0.5f / (BATCH * NPTS));
    } else {
        #pragma unroll
        for (int q = 0; q < 4; q++) {
            const int idx = tid + 256 * q;
            float mm = fminf(fminf(g_d3[idx], g_d3[1024 + idx]),
                             fminf(g_d3[2048 + idx], g_d3[3072 + idx]));
            a += sqrtf(fmaxf(mm, 0.0f)) * (0.5f / (BATCH * KPT));
        }
        if (tid < 24) a += g_slots[tid];
    }

    red[tid] = a;
    __syncthreads();
    #pragma unroll
    for (int s = THREADS / 2; s > 0; s >>= 1) {
        if (tid < s) red[tid] += red[tid + s];
        __syncthreads();
    }
    if (tid == 0) g_bsum[bid] = red[0];
}

__global__ void pass3(float* __restrict__ out) {
    const int tid = threadIdx.x;
    float a = (tid < 129) ? g_bsum[tid] : 0.0f;
    __shared__ float red[THREADS];
    red[tid] = a;
    __syncthreads();
    #pragma unroll
    for (int s = THREADS / 2; s > 0; s >>= 1) {
        if (tid < s) red[tid] += red[tid + s];
        __syncthreads();
    }
    if (tid == 0) out[0] = red[0];
}

extern "C" void kernel_launch(void* const* d_in, const int* in_sizes, int n_in,
                              void* d_out, int out_size) {
    const float* pts         = (const float*)d_in[0];
    const float* recon_delta = (const float*)d_in[1];
    const float* kpt         = (const float*)d_in[2];
    const float* recon       = (const float*)d_in[3];
    const float* pred_nocs   = (const float*)d_in[4];
    const float* pred_R      = (const float*)d_in[5];
    const float* pred_t      = (const float*)d_in[6];
    const float* pred_s      = (const float*)d_in[7];
    const float* gt_R        = (const float*)d_in[8];
    const float* gt_t        = (const float*)d_in[9];
    const float* gt_s        = (const float*)d_in[10];

    passA<<<296, THREADS>>>(pts, recon, kpt, recon_delta, pred_nocs,
                            pred_R, pred_t, pred_s, gt_R, gt_t, gt_s);
    pass2<<<129, THREADS>>>();
    pass3<<<1, THREADS>>>((float*)d_out);
}

// round 6
// speedup vs baseline: 2.1679x; 1.1031x over previous
#include <cuda_runtime.h>
#include <math.h>

#define BATCH 8
#define NPTS 2048
#define KPT 128
#define THREADS 256
#define NSLICE 24

typedef unsigned long long u64;

__device__ __forceinline__ u64 pack2(float lo, float hi) {
    u64 r;
    asm("mov.b64 %0, {%1, %2};" : "=l"(r) : "f"(lo), "f"(hi));
    return r;
}
__device__ __forceinline__ void unpack2(u64 v, float& lo, float& hi) {
    asm("mov.b64 {%0, %1}, %2;" : "=f"(lo), "=f"(hi) : "l"(v));
}
__device__ __forceinline__ u64 fma2(u64 a, u64 b, u64 c) {
    u64 d;
    asm("fma.rn.f32x2 %0, %1, %2, %3;" : "=l"(d) : "l"(a), "l"(b), "l"(c));
    return d;
}

// dir0/dir1 partial min-d^2: g_part24[slice][dir*16384 + b*2048 + row]
__device__ float g_part24[NSLICE * 32768];
// dir3 partials: g_d3[quarter][b*128 + r]
__device__ float g_d3[4 * 1024];
// slots: [0..15] dir2 item sums, [16..23] per-batch small losses
__device__ float g_slots[24];
// per-block sums from pass2
__device__ float g_bsum[129];

__device__ __forceinline__ float block_reduce_256(float v, float* red) {
    const int tid = threadIdx.x;
    red[tid] = v;
    __syncthreads();
    #pragma unroll
    for (int s = THREADS / 2; s > 0; s >>= 1) {
        if (tid < s) red[tid] += red[tid + s];
        __syncthreads();
    }
    return red[0];
}

__global__ void __launch_bounds__(THREADS, 3)
passA(const float* __restrict__ pts,
      const float* __restrict__ recon,
      const float* __restrict__ kpt,
      const float* __restrict__ recon_delta,
      const float* __restrict__ pred_nocs,
      const float* __restrict__ pred_R,
      const float* __restrict__ pred_t,
      const float* __restrict__ pred_s,
      const float* __restrict__ gt_R,
      const float* __restrict__ gt_t,
      const float* __restrict__ gt_s) {
    __shared__ __align__(16) unsigned char s_buf[8192];
    __shared__ float s_red[THREADS];

    const int bid = blockIdx.x;
    const int tid = threadIdx.x;

    if (bid < 384) {
        // ===== heavy: dir0/dir1, 2048 rows (8/thread), ~85-target slice =====
        const int dir = bid / 192;
        const int rem = bid - dir * 192;
        const int b   = rem / NSLICE;
        const int s   = rem - b * NSLICE;
        const int ts  = (s * 2048) / NSLICE;
        const int te  = ((s + 1) * 2048) / NSLICE;
        const int len = te - ts;

        const float* Q = (dir == 0 ? pts : recon) + (size_t)b * NPTS * 3;
        const float* T = (dir == 0 ? recon : pts) + (size_t)b * NPTS * 3 + ts * 3;

        // duplicated target tile: A[j]=((nx,nx),(ny,ny)), B[j]=((nz,nz),(w,w))
        ulonglong2* A = (ulonglong2*)s_buf;
        ulonglong2* B = A + 128;  // 2KB in
        if (tid < len) {
            float x = T[tid * 3 + 0];
            float y = T[tid * 3 + 1];
            float z = T[tid * 3 + 2];
            float w = fmaf(x, x, fmaf(y, y, z * z));
            float nx = -2.0f * x, ny = -2.0f * y, nz = -2.0f * z;
            A[tid] = make_ulonglong2(pack2(nx, nx), pack2(ny, ny));
            B[tid] = make_ulonglong2(pack2(nz, nz), pack2(w, w));
        }
        __syncthreads();

        // 8 query rows per thread, packed in row-pairs
        float q2[8];
        u64 X[4], Y[4], Z[4];
        {
            float qx[8], qy[8], qz[8];
            #pragma unroll
            for (int q = 0; q < 8; q++) {
                const int r = tid + 256 * q;
                qx[q] = Q[r * 3 + 0];
                qy[q] = Q[r * 3 + 1];
                qz[q] = Q[r * 3 + 2];
                q2[q] = fmaf(qx[q], qx[q], fmaf(qy[q], qy[q], qz[q] * qz[q]));
            }
            #pragma unroll
            for (int p = 0; p < 4; p++) {
                X[p] = pack2(qx[2 * p], qx[2 * p + 1]);
                Y[p] = pack2(qy[2 * p], qy[2 * p + 1]);
                Z[p] = pack2(qz[2 * p], qz[2 * p + 1]);
            }
        }

        float m[8];
        #pragma unroll
        for (int q = 0; q < 8; q++) m[q] = 3.0e38f;

        #pragma unroll 4
        for (int t = 0; t < len; t++) {
            ulonglong2 a = A[t];
            ulonglong2 c = B[t];
            #pragma unroll
            for (int p = 0; p < 4; p++) {
                u64 v = fma2(a.x, X[p], fma2(a.y, Y[p], fma2(c.x, Z[p], c.y)));
                float lo, hi;
                unpack2(v, lo, hi);
                m[2 * p]     = fminf(m[2 * p], lo);
                m[2 * p + 1] = fminf(m[2 * p + 1], hi);
            }
        }

        float* dst = g_part24 + (size_t)s * 32768 + dir * 16384 + b * 2048;
        #pragma unroll
        for (int q = 0; q < 8; q++) dst[tid + 256 * q] = q2[q] + m[q];
        return;
    }

    // ===== light items on blocks 384..443 (60 blocks, 56 items) =====
    {
        const int id = bid - 384;
        if (id >= 56) return;
        if (id < 16) {
            // dir2: pts -> kpt, 1024-row half, full 128 targets
            const int b = id >> 1;
            const int half = id & 1;
            const float* Q = pts + (size_t)b * NPTS * 3;
            const float* T = kpt + (size_t)b * KPT * 3;
            float4* tile = (float4*)s_buf;
            if (tid < KPT) {
                float x = T[tid * 3 + 0];
                float y = T[tid * 3 + 1];
                float z = T[tid * 3 + 2];
                float w = fmaf(x, x, fmaf(y, y, z * z));
                tile[tid] = make_float4(-2.0f * x, -2.0f * y, -2.0f * z, w);
            }
            __syncthreads();

            const int rowbase = half * 1024;
            float sum = 0.0f;
            #pragma unroll
            for (int q = 0; q < 4; q++) {
                const int r = rowbase + tid + 256 * q;
                float qx = Q[r * 3 + 0];
                float qy = Q[r * 3 + 1];
                float qz = Q[r * 3 + 2];
                float q2 = fmaf(qx, qx, fmaf(qy, qy, qz * qz));
                float mm = 3.0e38f;
                #pragma unroll 8
                for (int t = 0; t < KPT; t++) {
                    float4 sv = tile[t];
                    float v = fmaf(sv.x, qx, fmaf(sv.y, qy, fmaf(sv.z, qz, sv.w)));
                    mm = fminf(mm, v);
                }
                sum += sqrtf(fmaxf(q2 + mm, 0.0f));
            }
            float tot = block_reduce_256(sum, s_red);
            if (tid == 0) g_slots[id] = tot * (0.5f / (BATCH * NPTS));
        } else if (id < 48) {
            // dir3: kpt -> pts, 512-target quarter -> partial
            const int j = id - 16;
            const int b = j >> 2;
            const int quarter = j & 3;
            const float* Q = kpt + (size_t)b * KPT * 3;
            const float* T = pts + (size_t)b * NPTS * 3 + quarter * 512 * 3;
            float4* tile = (float4*)s_buf;
            for (int jj = tid; jj < 512; jj += THREADS) {
                float x = T[jj * 3 + 0];
                float y = T[jj * 3 + 1];
                float z = T[jj * 3 + 2];
                float w = fmaf(x, x, fmaf(y, y, z * z));
                tile[jj] = make_float4(-2.0f * x, -2.0f * y, -2.0f * z, w);
            }
            __syncthreads();

            if (tid < KPT) {
                float qx = Q[tid * 3 + 0];
                float qy = Q[tid * 3 + 1];
                float qz = Q[tid * 3 + 2];
                float q2 = fmaf(qx, qx, fmaf(qy, qy, qz * qz));
                float mm = 3.0e38f;
                #pragma unroll 8
                for (int t = 0; t < 512; t++) {
                    float4 sv = tile[t];
                    float v = fmaf(sv.x, qx, fmaf(sv.y, qy, fmaf(sv.z, qz, sv.w)));
                    mm = fminf(mm, v);
                }
                g_d3[quarter * 1024 + b * KPT + tid] = q2 + mm;
            }
        } else {
            // smalls: pose + NOCS + diversity + delta per batch
            const int b = id - 48;
            float* sk = (float*)s_buf;
            const float* K = kpt + (size_t)b * KPT * 3;
            for (int i = tid; i < KPT * 3; i += THREADS) sk[i] = K[i];
            __syncthreads();

            float acc = 0.0f;
            const float invDiv = 1.0f / (float)(BATCH * KPT * KPT);
            for (int p = tid; p < KPT * KPT; p += THREADS) {
                const int i = p >> 7;
                const int jj = p & 127;
                float c;
                if (i == jj) {
                    c = 0.1f;
                } else {
                    float dx = sk[i * 3 + 0] - sk[jj * 3 + 0];
                    float dy = sk[i * 3 + 1] - sk[jj * 3 + 1];
                    float dz = sk[i * 3 + 2] - sk[jj * 3 + 2];
                    c = fminf(sqrtf(fmaf(dx, dx, fmaf(dy, dy, dz * dz))), 0.1f);
                }
                acc += c * invDiv;
            }

            if (tid < KPT) {
                const float* R = gt_R + (size_t)b * 9;
                const float t0 = gt_t[b * 3 + 0], t1 = gt_t[b * 3 + 1], t2 = gt_t[b * 3 + 2];
                const float s0 = gt_s[b * 3 + 0], s1 = gt_s[b * 3 + 1], s2 = gt_s[b * 3 + 2];
                const float scale = sqrtf(s0 * s0 + s1 * s1 + s2 * s2) + 1e-8f;
                const float inv = 1.0f / scale;
                const float px = (sk[tid * 3 + 0] - t0) * inv;
                const float py = (sk[tid * 3 + 1] - t1) * inv;
                const float pz = (sk[tid * 3 + 2] - t2) * inv;
                const float* pn = pred_nocs + ((size_t)b * KPT + tid) * 3;
                float sl = 0.0f;
                #pragma unroll
                for (int jj = 0; jj < 3; jj++) {
                    float g = px * R[jj] + py * R[3 + jj] + pz * R[6 + jj];
                    float d = fabsf(pn[jj] - g);
                    sl += (d > 0.1f) ? (d - 0.05f) : (d * d * 5.0f);
                }
                acc += sl * (1.0f / (float)(BATCH * KPT));
            }

            const float* D = recon_delta + (size_t)b * NPTS * 3;
            float dsum = 0.0f;
            for (int r = tid; r < NPTS; r += THREADS) {
                float x = D[r * 3 + 0];
                float y = D[r * 3 + 1];
                float z = D[r * 3 + 2];
                dsum += sqrtf(fmaf(x, x, fmaf(y, y, z * z)));
            }
            acc += dsum * (1.0f / (float)(BATCH * NPTS));

            float tot = block_reduce_256(acc, s_red);
            if (tid == 0) {
                const float* Rp = pred_R + (size_t)b * 9;
                const float* Rg = gt_R + (size_t)b * 9;
                float cs = 0.0f;
                #pragma unroll
                for (int jj = 0; jj < 3; jj++) {
                    float a0 = Rp[jj]     - Rg[jj];
                    float a1 = Rp[3 + jj] - Rg[3 + jj];
                    float a2 = Rp[6 + jj] - Rg[6 + jj];
                    cs += sqrtf(a0 * a0 + a1 * a1 + a2 * a2);
                }
                float dt0 = pred_t[b * 3 + 0] - gt_t[b * 3 + 0];
                float dt1 = pred_t[b * 3 + 1] - gt_t[b * 3 + 1];
                float dt2 = pred_t[b * 3 + 2] - gt_t[b * 3 + 2];
                float tn = sqrtf(dt0 * dt0 + dt1 * dt1 + dt2 * dt2);
                float ds0 = pred_s[b * 3 + 0] - gt_s[b * 3 + 0];
                float ds1 = pred_s[b * 3 + 1] - gt_s[b * 3 + 1];
                float ds2 = pred_s[b * 3 + 2] - gt_s[b * 3 + 2];
                float sn = sqrtf(ds0 * ds0 + ds1 * ds1 + ds2 * ds2);
                g_slots[16 + b] = tot
                                + cs * (1.0f / (3.0f * BATCH))
                                + tn * (1.0f / BATCH)
                                + sn * (1.0f / BATCH);
            }
        }
    }
}

__global__ void pass2() {
    __shared__ float red[THREADS];
    const int bid = blockIdx.x;
    const int tid = threadIdx.x;
    float a = 0.0f;

    if (bid < 128) {
        const int row = bid * 256 + tid;
        float m0 = 3.0e38f, m1 = 3.0e38f, m2 = 3.0e38f, m3 = 3.0e38f;
        #pragma unroll
        for (int s = 0; s < NSLICE; s += 4) {
            m0 = fminf(m0, g_part24[(s + 0) * 32768 + row]);
            m1 = fminf(m1, g_part24[(s + 1) * 32768 + row]);
            m2 = fminf(m2, g_part24[(s + 2) * 32768 + row]);
            m3 = fminf(m3, g_part24[(s + 3) * 32768 + row]);
        }
        float mm = fminf(fminf(m0, m1), fminf(m2, m3));
        a = sqrtf(fmaxf(mm, 0.0f)) * (0.5f / (BATCH * NPTS));
    } else {
        #pragma unroll
        for (int q = 0; q < 4; q++) {
            const int idx = tid + 256 * q;
            float mm = fminf(fminf(g_d3[idx], g_d3[1024 + idx]),
                             fminf(g_d3[2048 + idx], g_d3[3072 + idx]));
            a += sqrtf(fmaxf(mm, 0.0f)) * (0.5f / (BATCH * KPT));
        }
        if (tid < 24) a += g_slots[tid];
    }

    red[tid] = a;
    __syncthreads();
    #pragma unroll
    for (int s = THREADS / 2; s > 0; s >>= 1) {
        if (tid < s) red[tid] += red[tid + s];
        __syncthreads();
    }
    if (tid == 0) g_bsum[bid] = red[0];
}

__global__ void pass3(float* __restrict__ out) {
    const int tid = threadIdx.x;
    float a = (tid < 129) ? g_bsum[tid] : 0.0f;
    __shared__ float red[THREADS];
    red[tid] = a;
    __syncthreads();
    #pragma unroll
    for (int s = THREADS / 2; s > 0; s >>= 1) {
        if (tid < s) red[tid] += red[tid + s];
        __syncthreads();
    }
    if (tid == 0) out[0] = red[0];
}

extern "C" void kernel_launch(void* const* d_in, const int* in_sizes, int n_in,
                              void* d_out, int out_size) {
    const float* pts         = (const float*)d_in[0];
    const float* recon_delta = (const float*)d_in[1];
    const float* kpt         = (const float*)d_in[2];
    const float* recon       = (const float*)d_in[3];
    const float* pred_nocs   = (const float*)d_in[4];
    const float* pred_R      = (const float*)d_in[5];
    const float* pred_t      = (const float*)d_in[6];
    const float* pred_s      = (const float*)d_in[7];
    const float* gt_R        = (const float*)d_in[8];
    const float* gt_t        = (const float*)d_in[9];
    const float* gt_s        = (const float*)d_in[10];

    passA<<<444, THREADS>>>(pts, recon, kpt, recon_delta, pred_nocs,
                            pred_R, pred_t, pred_s, gt_R, gt_t, gt_s);
    pass2<<<129, THREADS>>>();
    pass3<<<1, THREADS>>>((float*)d_out);
}